// round 16
// baseline (speedup 1.0000x reference)
#include <cuda_runtime.h>
#include <cuda_fp16.h>
#include <cstdint>

#define BATCH 256
#define TSEQ  2048
#define DH    512
#define STEPS 2040
#define DIN   384

__device__ float g_hx[(size_t)BATCH * STEPS * DH];

__device__ __forceinline__ unsigned su32(const void* p) {
    return (unsigned)__cvta_generic_to_shared(p);
}
__device__ __forceinline__ void ldsm4(unsigned* r, unsigned a) {
    asm volatile("ldmatrix.sync.aligned.m8n8.x4.shared.b16 {%0,%1,%2,%3}, [%4];"
                 : "=r"(r[0]), "=r"(r[1]), "=r"(r[2]), "=r"(r[3]) : "r"(a));
}
__device__ __forceinline__ void ldsm2(unsigned& r0, unsigned& r1, unsigned a) {
    asm volatile("ldmatrix.sync.aligned.m8n8.x2.shared.b16 {%0,%1}, [%2];"
                 : "=r"(r0), "=r"(r1) : "r"(a));
}
__device__ __forceinline__ void mma16816(float* c, const unsigned* a, unsigned b0, unsigned b1) {
    asm volatile("mma.sync.aligned.m16n8k16.row.col.f32.f16.f16.f32 "
                 "{%0,%1,%2,%3}, {%4,%5,%6,%7}, {%8,%9}, {%0,%1,%2,%3};"
                 : "+f"(c[0]), "+f"(c[1]), "+f"(c[2]), "+f"(c[3])
                 : "r"(a[0]), "r"(a[1]), "r"(a[2]), "r"(a[3]), "r"(b0), "r"(b1));
}
__device__ __forceinline__ float tanh_fast(float v) {
    float r; asm("tanh.approx.f32 %0, %1;" : "=f"(r) : "f"(v)); return r;
}

// ===========================================================================
// Phase A: Hx = Xwin[128t x 256k] @ W1x^T, fp16 mma  (passing version, verbatim)
// ===========================================================================
#define WS_LD 264
#define CB_LD 132
#define XSP   5408

__global__ void __launch_bounds__(256, 2)
narx_hx(const float* __restrict__ x, const float* __restrict__ W1,
        const float* __restrict__ b1)
{
    extern __shared__ unsigned char smraw[];
    __half* xs = (__half*)smraw;
    __half* ws = (__half*)(smraw + XSP * 2);
    float*  cb = (float*)(smraw + XSP * 2);

    const int tid = threadIdx.x, warp = tid >> 5, lane = tid & 31;
    const int wm = warp & 1, wn = warp >> 1;
    const int t0 = blockIdx.x * 128, J0 = blockIdx.y * 128, b = blockIdx.z;

    {
        const float* xb = x + (size_t)b * (TSEQ * 32) + (size_t)t0 * 32;
        const int lim = TSEQ * 32 - t0 * 32;
        for (int i = tid; i < 4320; i += 256) {
            float v = (i < lim) ? xb[i] : 0.0f;
            xs[(i >> 5) * 40 + (i & 31)] = __float2half_rn(v);
        }
    }
    for (int idx = tid; idx < 128 * 128; idx += 256) {
        int j = idx >> 7, k2 = (idx & 127) << 1;
        const float* w = W1 + (size_t)(J0 + j) * DIN + k2;
        *(__half2*)(ws + j * WS_LD + k2) = __floats2half2_rn(w[0], w[1]);
    }
    __syncthreads();

    float c[4][4][4];
    #pragma unroll
    for (int i = 0; i < 4; i++)
        #pragma unroll
        for (int j = 0; j < 4; j++)
            #pragma unroll
            for (int r = 0; r < 4; r++) c[i][j][r] = 0.0f;

    const unsigned xsb = su32(xs), wsb = su32(ws);
    const int mat = lane >> 3, lrow = lane & 7;

    #pragma unroll 4
    for (int ks = 0; ks < 16; ++ks) {
        unsigned a[4][4], b0[4], b1[4];
        const int col = ks * 16 + (mat >> 1) * 8;
        const int ce  = (col >> 5) * 40 + (col & 31);
        #pragma unroll
        for (int mt = 0; mt < 4; ++mt) {
            int row = wm * 64 + mt * 16 + (mat & 1) * 8 + lrow;
            ldsm4(a[mt], xsb + 2u * (unsigned)(row * 40 + ce));
        }
        const int bcol = ks * 16 + ((lane >> 3) & 1) * 8;
        #pragma unroll
        for (int nt = 0; nt < 4; ++nt) {
            int br = wn * 32 + nt * 8 + lrow;
            ldsm2(b0[nt], b1[nt], wsb + 2u * (unsigned)(br * WS_LD + bcol));
        }
        #pragma unroll
        for (int mt = 0; mt < 4; ++mt)
            #pragma unroll
            for (int nt = 0; nt < 4; ++nt)
                mma16816(c[mt][nt], a[mt], b0[nt], b1[nt]);
    }

    __syncthreads();
    {
        const int g = lane >> 2, tq = lane & 3;
        #pragma unroll
        for (int mt = 0; mt < 4; ++mt)
            #pragma unroll
            for (int nt = 0; nt < 4; ++nt) {
                int m0 = wm * 64 + mt * 16 + g, n0 = wn * 32 + nt * 8 + tq * 2;
                *(float2*)(cb + m0 * CB_LD + n0) = make_float2(c[mt][nt][0], c[mt][nt][1]);
                *(float2*)(cb + (m0 + 8) * CB_LD + n0) = make_float2(c[mt][nt][2], c[mt][nt][3]);
            }
    }
    __syncthreads();
    {
        const float4 bv = *(const float4*)(b1 + J0 + lane * 4);
        #pragma unroll 4
        for (int rr = 0; rr < 16; ++rr) {
            int row = warp * 16 + rr, t = t0 + row;
            if (t < STEPS) {
                float4 v = *(float4*)(cb + row * CB_LD + lane * 4);
                v.x += bv.x; v.y += bv.y; v.z += bv.z; v.w += bv.w;
                *(float4*)(g_hx + ((size_t)b * STEPS + t) * DH + J0 + lane * 4) = v;
            }
        }
    }
}

// ===========================================================================
// Phase B: both layers on tensor pipe + PIPELINED feedback: carry accumulator
// fb[] = prefetched Hx(next) + old-y contributions (12 background HMMA);
// critical path per step = 4 newest-y HMMA + tanh + L2 mma + reduce.
// ===========================================================================
#define YLD 136
#define HLD 520
#define OFF_YS   139264
#define OFF_HARR 141440
#define OFF_PBUF 149760
#define OFF_SB2  153856
#define SMB_TOT  154112

__global__ void __launch_bounds__(512, 1)
narx_recur(const float* __restrict__ W1, const float* __restrict__ W2,
           const float* __restrict__ b2, float* __restrict__ out)
{
    extern __shared__ unsigned char smraw[];
    __half* wf   = (__half*)smraw;                   // staging (wf, then W2)
    __half* ys   = (__half*)(smraw + OFF_YS);
    __half* harr = (__half*)(smraw + OFF_HARR);
    float*  pbuf = (float*)(smraw + OFF_PBUF);
    float*  sb2  = (float*)(smraw + OFF_SB2);

    const int tid = threadIdx.x, warp = tid >> 5, lane = tid & 31;
    const int b0 = blockIdx.x * 2;
    const int jb = warp * 32;
    const int mat = lane >> 3, lrow = lane & 7;

    // ---- stage Wf = W1[:,256:384] fp16, zero ys + harr ----
    for (int idx = tid; idx < 512 * 64; idx += 512) {
        int j = idx >> 6, q2 = (idx & 63) << 1;
        const float* s = W1 + (size_t)j * DIN + 256 + q2;
        *(__half2*)(wf + j * YLD + q2) = __floats2half2_rn(s[0], s[1]);
    }
    for (int idx = tid; idx < 8 * YLD; idx += 512) ys[idx] = __float2half_rn(0.0f);
    for (int idx = tid; idx < 8 * HLD; idx += 512) harr[idx] = __float2half_rn(0.0f);
    if (tid < 64) sb2[tid] = b2[tid >> 1];
    __syncthreads();

    unsigned wfr[2][8][4];
    {
        const unsigned wfb = su32(wf);
        #pragma unroll
        for (int mt = 0; mt < 2; ++mt)
            #pragma unroll
            for (int kt = 0; kt < 8; ++kt) {
                int j = jb + mt * 16 + (mat & 1) * 8 + lrow;
                int q = kt * 16 + (mat >> 1) * 8;
                ldsm4(wfr[mt][kt], wfb + 2u * (unsigned)(j * YLD + q));
            }
    }
    __syncthreads();

    {   // stage W2 [32 m][520] fp16 into dead wf area
        __half* w2h = wf;
        for (int idx = tid; idx < 32 * 256; idx += 512) {
            int m = idx >> 8, j2 = (idx & 255) << 1;
            const float* s = W2 + (size_t)m * DH + j2;
            *(__half2*)(w2h + m * HLD + j2) = __floats2half2_rn(s[0], s[1]);
        }
    }
    __syncthreads();
    unsigned w2f[2][2][4];
    {
        const unsigned w2b = su32(wf);
        #pragma unroll
        for (int mt = 0; mt < 2; ++mt)
            #pragma unroll
            for (int kt = 0; kt < 2; ++kt) {
                int m = mt * 16 + (mat & 1) * 8 + lrow;
                int k = jb + kt * 16 + (mat >> 1) * 8;
                ldsm4(w2f[mt][kt], w2b + 2u * (unsigned)(m * HLD + k));
            }
    }
    __syncthreads();

    const float* hx0 = g_hx + (size_t)b0 * STEPS * DH;
    const float* hx1 = hx0 + (size_t)STEPS * DH;
    const int m8 = lane >> 2;
    const int ja = jb + m8, jc = jb + 16 + m8;
    const __half* ybase = ys + (lane >> 2) * YLD + (lane & 3) * 2;
    const unsigned lsAddr = su32(harr) + 2u * (unsigned)(lrow * HLD + jb + ((lane >> 3) & 1) * 8);
    float* pw = pbuf + warp * 64;
    float* optr = out + (size_t)(b0 + (tid & 1)) * STEPS * 32 + (tid >> 1);
    const int ywi = (tid & 1) * YLD + (tid >> 1);

    // fb carry accumulator: Hx(step i) + old-y feedback. Init = Hx_0.
    float fb0[4], fb1[4];
    fb0[0] = __ldcs(hx0 + ja);      fb0[1] = __ldcs(hx1 + ja);
    fb0[2] = __ldcs(hx0 + ja + 8);  fb0[3] = __ldcs(hx1 + ja + 8);
    fb1[0] = __ldcs(hx0 + jc);      fb1[1] = __ldcs(hx1 + jc);
    fb1[2] = __ldcs(hx0 + jc + 8);  fb1[3] = __ldcs(hx1 + jc + 8);
    const float* pf0 = hx0 + DH;
    const float* pf1 = hx1 + DH;

    for (int i = 0; i < STEPS; i += 4) {
        #pragma unroll
        for (int u = 0; u < 4; ++u) {
            float c0[4] = {fb0[0], fb0[1], fb0[2], fb0[3]};
            float c1[4] = {fb1[0], fb1[1], fb1[2], fb1[3]};

            // CRITICAL: newest y_{i-1} (Wf kt=6,7), slot (u+3)&3
            {
                const int s3 = ((u + 3) & 3) << 5;
                unsigned a0 = *(const unsigned*)(ybase + s3);
                unsigned a1 = *(const unsigned*)(ybase + s3 + 8);
                unsigned a2 = *(const unsigned*)(ybase + s3 + 16);
                unsigned a3 = *(const unsigned*)(ybase + s3 + 24);
                mma16816(c0, wfr[0][6], a0, a1);
                mma16816(c1, wfr[1][6], a0, a1);
                mma16816(c0, wfr[0][7], a2, a3);
                mma16816(c1, wfr[1][7], a2, a3);
            }

            // prefetch next Hx into fb (C-init for background mma)
            if (i + u + 1 < STEPS) {
                const float* q0 = pf0 + u * DH;
                const float* q1 = pf1 + u * DH;
                fb0[0] = __ldcs(q0 + ja);     fb0[1] = __ldcs(q1 + ja);
                fb0[2] = __ldcs(q0 + ja + 8); fb0[3] = __ldcs(q1 + ja + 8);
                fb1[0] = __ldcs(q0 + jc);     fb1[1] = __ldcs(q1 + jc);
                fb1[2] = __ldcs(q0 + jc + 8); fb1[3] = __ldcs(q1 + jc + 8);
            }

            // BACKGROUND: old-y contributions for NEXT step (kt=0..5),
            // slot = (u+1+(kt>>1))&3 — compile-time; hazard-free (never slot u)
            #pragma unroll
            for (int kt = 0; kt < 6; ++kt) {
                const int off = (((u + 1 + (kt >> 1)) & 3) << 5) + ((kt & 1) << 4);
                unsigned bb0 = *(const unsigned*)(ybase + off);
                unsigned bb1 = *(const unsigned*)(ybase + off + 8);
                mma16816(fb0, wfr[0][kt], bb0, bb1);
                mma16816(fb1, wfr[1][kt], bb0, bb1);
            }

            // tanh -> fp16 h (rows 0,1 of harr; rows 2-7 stay zero)
            if ((lane & 3) == 0) {
                harr[ja]            = __float2half_rn(tanh_fast(c0[0]));
                harr[HLD + ja]      = __float2half_rn(tanh_fast(c0[1]));
                harr[ja + 8]        = __float2half_rn(tanh_fast(c0[2]));
                harr[HLD + ja + 8]  = __float2half_rn(tanh_fast(c0[3]));
                harr[jc]            = __float2half_rn(tanh_fast(c1[0]));
                harr[HLD + jc]      = __float2half_rn(tanh_fast(c1[1]));
                harr[jc + 8]        = __float2half_rn(tanh_fast(c1[2]));
                harr[HLD + jc + 8]  = __float2half_rn(tanh_fast(c1[3]));
            }
            __syncthreads();                     // (A) h ready

            // layer-2 GEMM: warp's k-chunk, D partial [32m x 2n]
            float d0[4] = {0.f, 0.f, 0.f, 0.f};
            float d1[4] = {0.f, 0.f, 0.f, 0.f};
            #pragma unroll
            for (int kt = 0; kt < 2; ++kt) {
                unsigned bb0, bb1;
                ldsm2(bb0, bb1, lsAddr + kt * 32u);
                mma16816(d0, w2f[0][kt], bb0, bb1);
                mma16816(d1, w2f[1][kt], bb0, bb1);
            }
            if ((lane & 3) == 0) {
                *(float2*)(pw + 2 * m8)        = make_float2(d0[0], d0[1]);
                *(float2*)(pw + 2 * (m8 + 8))  = make_float2(d0[2], d0[3]);
                *(float2*)(pw + 2 * (m8 + 16)) = make_float2(d1[0], d1[1]);
                *(float2*)(pw + 2 * (m8 + 24)) = make_float2(d1[2], d1[3]);
            }
            __syncthreads();                     // (B) partials ready

            if (tid < 64) {
                float z = sb2[tid];
                #pragma unroll
                for (int w = 0; w < 16; ++w) z += pbuf[w * 64 + tid];
                float o = __fdividef(1.0f, 1.0f + __expf(-z));
                ys[ywi + u * 32] = __float2half_rn(o);   // new-y slot = u&3
                optr[u * 32] = o;
            }
            __syncthreads();                     // (C) y ready
        }
        pf0 += 4 * DH; pf1 += 4 * DH; optr += 128;
    }
}

extern "C" void kernel_launch(void* const* d_in, const int* in_sizes, int n_in,
                              void* d_out, int out_size)
{
    const float* x  = (const float*)d_in[0];
    const float* W1 = (const float*)d_in[1];
    const float* b1 = (const float*)d_in[2];
    const float* W2 = (const float*)d_in[3];
    const float* b2 = (const float*)d_in[4];
    float* out = (float*)d_out;
    (void)in_sizes; (void)n_in; (void)out_size;

    constexpr size_t smA = XSP * 2 + 128 * WS_LD * 2;   // 78,400 B
    constexpr size_t smB = SMB_TOT;                     // 154,112 B

    cudaFuncSetAttribute(narx_hx, cudaFuncAttributeMaxDynamicSharedMemorySize, (int)smA);
    cudaFuncSetAttribute(narx_recur, cudaFuncAttributeMaxDynamicSharedMemorySize, (int)smB);

    dim3 gA(16, 4, 256);
    narx_hx<<<gA, 256, smA>>>(x, W1, b1);
    narx_recur<<<128, 512, smB>>>(W1, W2, b2, out);
}